// round 2
// baseline (speedup 1.0000x reference)
#include <cuda_runtime.h>

// Problem constants (fixed shapes per reference)
#define N_NODES 100000
#define N_EDGES 1600000
#define D 64
#define C_CLS 47
#define N_POW 50
#define CS_BLOCKS 240
#define SCAN_BLK 1024
#define N_SCAN_BLOCKS ((N_NODES + SCAN_BLK - 1) / SCAN_BLK)   // 98

// ---------- device scratch (static; no allocations allowed) ----------
__device__ int   g_y[N_NODES];             // canonical labels
__device__ int   g_tm[N_NODES];            // canonical train mask
__device__ int   g_isy;                    // disambiguation: max of candidate A
__device__ int   g_ecnt[N_NODES];          // #out-edges per node (excl self loop)
__device__ int   g_off[N_NODES];           // CSR offsets (exclusive scan of ecnt)
__device__ int   g_cursor[N_NODES];        // scatter cursors
__device__ int   g_colidx[N_EDGES];        // CSR column indices
__device__ float g_deginv[N_NODES];        // 1/(ecnt+1)
__device__ float g_colsum[D];              // column sums of x
__device__ int   g_classcnt[C_CLS];        // train count per class
__device__ float g_lblscale[N_NODES];      // tm[i] ? 1/(cnt[y_i]+1e-8) : 0
__device__ float g_xc[N_NODES * D];        // centered features
__device__ float g_v0[N_NODES * D];        // ping
__device__ float g_v1[N_NODES * D];        // pong
__device__ float g_cspart[CS_BLOCKS * C_CLS * D];  // per-block partial class sums
__device__ float g_cs[C_CLS * D];          // reduced class sums
__device__ int   g_blocksums[N_SCAN_BLOCKS];

// ---------- setup kernels ----------
__global__ void zero_setup_kernel() {
    int stride = gridDim.x * blockDim.x;
    for (int i = blockIdx.x * blockDim.x + threadIdx.x; i < N_NODES; i += stride) {
        g_ecnt[i] = 0;
        g_cursor[i] = 0;
    }
    int tid = blockIdx.x * blockDim.x + threadIdx.x;
    if (tid < D) g_colsum[tid] = 0.0f;
    if (tid < C_CLS) g_classcnt[tid] = 0;
    if (tid == 0) g_isy = 0;
}

// max-reduce candidate A to decide whether it is y (max>1) or train_mask
__global__ void disamb_kernel(const int* __restrict__ a) {
    int m = 0;
    int stride = gridDim.x * blockDim.x;
    for (int i = blockIdx.x * blockDim.x + threadIdx.x; i < N_NODES; i += stride)
        m = max(m, a[i]);
    #pragma unroll
    for (int s = 16; s > 0; s >>= 1)
        m = max(m, __shfl_xor_sync(0xffffffffu, m, s));
    if ((threadIdx.x & 31) == 0) atomicMax(&g_isy, m);
}

__global__ void canon_kernel(const int* __restrict__ a, const int* __restrict__ b) {
    bool a_is_y = (g_isy > 1);
    const int* yp = a_is_y ? a : b;
    const int* tp = a_is_y ? b : a;
    int stride = gridDim.x * blockDim.x;
    for (int i = blockIdx.x * blockDim.x + threadIdx.x; i < N_NODES; i += stride) {
        g_y[i] = yp[i];
        g_tm[i] = tp[i];
    }
}

__global__ void count_kernel(const int* __restrict__ row) {
    int stride = gridDim.x * blockDim.x;
    for (int e = blockIdx.x * blockDim.x + threadIdx.x; e < N_EDGES; e += stride)
        atomicAdd(&g_ecnt[row[e]], 1);
    for (int i = blockIdx.x * blockDim.x + threadIdx.x; i < N_NODES; i += stride)
        if (g_tm[i]) atomicAdd(&g_classcnt[g_y[i]], 1);
}

__global__ void scan1_kernel() {
    __shared__ int s[SCAN_BLK];
    int gid = blockIdx.x * SCAN_BLK + threadIdx.x;
    int val = (gid < N_NODES) ? g_ecnt[gid] : 0;
    s[threadIdx.x] = val;
    __syncthreads();
    for (int d = 1; d < SCAN_BLK; d <<= 1) {
        int t = (threadIdx.x >= (unsigned)d) ? s[threadIdx.x - d] : 0;
        __syncthreads();
        s[threadIdx.x] += t;
        __syncthreads();
    }
    if (gid < N_NODES) g_off[gid] = s[threadIdx.x] - val;  // exclusive
    if (threadIdx.x == SCAN_BLK - 1) g_blocksums[blockIdx.x] = s[SCAN_BLK - 1];
}

__global__ void scan2_kernel() {
    if (threadIdx.x == 0 && blockIdx.x == 0) {
        int running = 0;
        for (int b = 0; b < N_SCAN_BLOCKS; b++) {
            int t = g_blocksums[b];
            g_blocksums[b] = running;
            running += t;
        }
    }
}

__global__ void scan3_kernel() {
    int stride = gridDim.x * blockDim.x;
    for (int i = blockIdx.x * blockDim.x + threadIdx.x; i < N_NODES; i += stride) {
        g_off[i] += g_blocksums[i >> 10];
        g_deginv[i] = 1.0f / (float)(g_ecnt[i] + 1);   // +1 self loop
    }
}

__global__ void scatter_kernel(const int* __restrict__ row,
                               const int* __restrict__ col) {
    int stride = gridDim.x * blockDim.x;
    for (int e = blockIdx.x * blockDim.x + threadIdx.x; e < N_EDGES; e += stride) {
        int r = row[e];
        int pos = g_off[r] + atomicAdd(&g_cursor[r], 1);
        g_colidx[pos] = col[e];
    }
}

__global__ void colsum_kernel(const float* __restrict__ x) {
    __shared__ float s[D];
    if (threadIdx.x < D) s[threadIdx.x] = 0.0f;
    __syncthreads();
    float acc = 0.0f;
    int stride = gridDim.x * blockDim.x;  // multiple of 64 -> fixed column per thread
    for (int idx = blockIdx.x * blockDim.x + threadIdx.x; idx < N_NODES * D; idx += stride)
        acc += x[idx];
    atomicAdd(&s[threadIdx.x & (D - 1)], acc);
    __syncthreads();
    if (threadIdx.x < D) atomicAdd(&g_colsum[threadIdx.x], s[threadIdx.x]);
}

__global__ void init_kernel(const float* __restrict__ x) {
    int stride = gridDim.x * blockDim.x;
    const float invn = 1.0f / (float)N_NODES;
    for (int idx = blockIdx.x * blockDim.x + threadIdx.x; idx < N_NODES * D; idx += stride) {
        float v = x[idx] - g_colsum[idx & (D - 1)] * invn;
        g_xc[idx] = v;
        g_v0[idx] = v;
    }
    for (int i = blockIdx.x * blockDim.x + threadIdx.x; i < N_NODES; i += stride)
        g_tm[i] ? (g_lblscale[i] = 1.0f / ((float)g_classcnt[g_y[i]] + 1e-8f))
                : (g_lblscale[i] = 0.0f);
}

// ---------- per-iteration kernels ----------
// A: per-block partial class sums (direct store — no global atomics)
__global__ __launch_bounds__(256) void cs_partial_kernel(int parity) {
    const float* __restrict__ v = parity ? g_v1 : g_v0;
    __shared__ float s[C_CLS * D];
    for (int i = threadIdx.x; i < C_CLS * D; i += blockDim.x) s[i] = 0.0f;
    __syncthreads();
    int d = threadIdx.x & (D - 1);
    int sub = threadIdx.x >> 6;  // 0..3
    for (int i = blockIdx.x * 4 + sub; i < N_NODES; i += gridDim.x * 4) {
        if (g_tm[i]) atomicAdd(&s[g_y[i] * D + d], v[i * D + d]);
    }
    __syncthreads();
    float* part = g_cspart + (size_t)blockIdx.x * (C_CLS * D);
    for (int i = threadIdx.x; i < C_CLS * D; i += blockDim.x) part[i] = s[i];
}

// B: reduce partials -> g_cs
__global__ void cs_reduce_kernel() {
    int i = blockIdx.x * blockDim.x + threadIdx.x;
    if (i < C_CLS * D) {
        float a = 0.0f;
        for (int b = 0; b < CS_BLOCKS; b++) a += g_cspart[b * (C_CLS * D) + i];
        g_cs[i] = a;
    }
}

// C: warp per node. out = 0.45*deginv*(v[i]+sum nbrs) + 0.05*lblscale*cs[y] + 0.5*xc
__global__ __launch_bounds__(256) void power_iter_kernel(int parity) {
    const float* __restrict__ vin = parity ? g_v1 : g_v0;
    float* __restrict__ vout = parity ? g_v0 : g_v1;
    int warp = (blockIdx.x * blockDim.x + threadIdx.x) >> 5;
    int lane = threadIdx.x & 31;
    if (warp >= N_NODES) return;
    const int i = warp;
    const float2* __restrict__ v2 = (const float2*)vin;

    float2 acc = v2[i * 32 + lane];  // self loop contribution
    int off = g_off[i];
    int cnt = g_ecnt[i];
    for (int base = 0; base < cnt; base += 32) {
        int idx = 0;
        if (base + lane < cnt) idx = g_colidx[off + base + lane];
        int m = min(32, cnt - base);
        for (int k = 0; k < m; k++) {
            int j = __shfl_sync(0xffffffffu, idx, k);
            float2 t = v2[j * 32 + lane];
            acc.x += t.x;
            acc.y += t.y;
        }
    }
    float dinv = g_deginv[i];
    float ls = g_lblscale[i];
    float2 p2 = make_float2(0.0f, 0.0f);
    if (ls != 0.0f) {
        const float2* cs2 = (const float2*)g_cs;
        p2 = cs2[g_y[i] * 32 + lane];
    }
    const float2* xc2 = (const float2*)g_xc;
    float2 xcv = xc2[i * 32 + lane];
    float2 o;
    o.x = 0.45f * dinv * acc.x + 0.05f * ls * p2.x + 0.5f * xcv.x;
    o.y = 0.45f * dinv * acc.y + 0.05f * ls * p2.y + 0.5f * xcv.y;
    ((float2*)vout)[i * 32 + lane] = o;
}

// ---------- final GEMM: out = g_v0 @ W + bias ----------
__global__ __launch_bounds__(256) void gemm_kernel(const float* __restrict__ W,
                                                   const float* __restrict__ bias,
                                                   float* __restrict__ out) {
    __shared__ float sW[D * D];
    __shared__ float sB[D];
    for (int i = threadIdx.x; i < D * D; i += blockDim.x) sW[i] = W[i];
    if (threadIdx.x < D) sB[threadIdx.x] = bias[threadIdx.x];
    __syncthreads();
    int warp = (blockIdx.x * blockDim.x + threadIdx.x) >> 5;
    int lane = threadIdx.x & 31;
    if (warp >= N_NODES) return;
    const float2* v2 = (const float2*)g_v0;
    float2 myv = v2[warp * 32 + lane];  // columns 2*lane, 2*lane+1 of v row
    float2 acc = make_float2(sB[2 * lane], sB[2 * lane + 1]);
    #pragma unroll
    for (int k = 0; k < 32; k++) {
        float a = __shfl_sync(0xffffffffu, myv.x, k);  // v[i][2k]
        float b = __shfl_sync(0xffffffffu, myv.y, k);  // v[i][2k+1]
        acc.x += a * sW[(2 * k) * D + 2 * lane]     + b * sW[(2 * k + 1) * D + 2 * lane];
        acc.y += a * sW[(2 * k) * D + 2 * lane + 1] + b * sW[(2 * k + 1) * D + 2 * lane + 1];
    }
    ((float2*)out)[warp * 32 + lane] = acc;
}

// ---------- launch ----------
extern "C" void kernel_launch(void* const* d_in, const int* in_sizes, int n_in,
                              void* d_out, int out_size) {
    // Resolve inputs by unique element counts; the two 100k int arrays (y,
    // train_mask) are disambiguated on-device.
    const float* x = nullptr;
    const float* W = nullptr;
    const float* bias = nullptr;
    const int* ei = nullptr;
    const int* nb[2] = {nullptr, nullptr};
    int nbi = 0;
    for (int i = 0; i < n_in; i++) {
        switch (in_sizes[i]) {
            case N_NODES * D:   x = (const float*)d_in[i]; break;
            case D * D:         W = (const float*)d_in[i]; break;
            case D:             bias = (const float*)d_in[i]; break;
            case 2 * N_EDGES:   ei = (const int*)d_in[i]; break;
            case N_NODES:       if (nbi < 2) nb[nbi++] = (const int*)d_in[i]; break;
            default: break;
        }
    }
    float* out = (float*)d_out;
    const int* row = ei;            // edge_index[0]
    const int* col = ei + N_EDGES;  // edge_index[1]

    // ---- one-time setup (inside graph, amortized over 50 iterations) ----
    zero_setup_kernel<<<256, 256>>>();
    disamb_kernel<<<128, 256>>>(nb[0]);
    canon_kernel<<<256, 256>>>(nb[0], nb[1]);
    count_kernel<<<512, 256>>>(row);
    scan1_kernel<<<N_SCAN_BLOCKS, SCAN_BLK>>>();
    scan2_kernel<<<1, 32>>>();
    scan3_kernel<<<256, 256>>>();
    scatter_kernel<<<512, 256>>>(row, col);
    colsum_kernel<<<256, 256>>>(x);
    init_kernel<<<512, 256>>>(x);

    // ---- 50 power iterations, ping-pong g_v0/g_v1 via parity ----
    const int bblocks = (N_NODES * 32 + 255) / 256;  // warp per node
    for (int it = 0; it < N_POW; it++) {
        const int parity = it & 1;   // 0: read v0 write v1; 1: read v1 write v0
        cs_partial_kernel<<<CS_BLOCKS, 256>>>(parity);
        cs_reduce_kernel<<<(C_CLS * D + 255) / 256, 256>>>();
        power_iter_kernel<<<bblocks, 256>>>(parity);
    }

    // 50 iterations (even) => result is in g_v0
    gemm_kernel<<<bblocks, 256>>>(W, bias, out);
}

// round 3
// speedup vs baseline: 1.6065x; 1.6065x over previous
#include <cuda_runtime.h>

// Problem constants (fixed shapes per reference)
#define N_NODES 100000
#define N_EDGES 1600000
#define D 64
#define C_CLS 47
#define N_POW 50
#define SCAN_BLK 1024
#define N_SCAN_BLOCKS ((N_NODES + SCAN_BLK - 1) / SCAN_BLK)   // 98

// ---------- device scratch (static; no allocations allowed) ----------
__device__ int   g_y[N_NODES];
__device__ int   g_tm[N_NODES];
__device__ int   g_isy;
__device__ int   g_ecnt[N_NODES];
__device__ int   g_off[N_NODES];
__device__ int   g_cursor[N_NODES];
__device__ int   g_colidx[N_EDGES];
__device__ float g_deginv[N_NODES];
__device__ float g_colsum[D];
__device__ int   g_classcnt[C_CLS];
__device__ float g_lblscale[N_NODES];
__device__ float g_xc[N_NODES * D];
__device__ float g_v0[N_NODES * D];
__device__ float g_v1[N_NODES * D];
__device__ float g_cs3[3][C_CLS * D];      // rotating class-sum buffers
__device__ int   g_blocksums[N_SCAN_BLOCKS];

// ---------- setup kernels ----------
__global__ void zero_setup_kernel() {
    int stride = gridDim.x * blockDim.x;
    int tid = blockIdx.x * blockDim.x + threadIdx.x;
    for (int i = tid; i < N_NODES; i += stride) {
        g_ecnt[i] = 0;
        g_cursor[i] = 0;
    }
    // zero all 3 cs buffers (cs[0] gets init-time accumulation)
    for (int i = tid; i < 3 * C_CLS * D; i += stride)
        ((float*)g_cs3)[i] = 0.0f;
    if (tid < D) g_colsum[tid] = 0.0f;
    if (tid < C_CLS) g_classcnt[tid] = 0;
    if (tid == 0) g_isy = 0;
}

// max-reduce candidate A: max>1 => it's y, else it's train_mask
__global__ void disamb_kernel(const int* __restrict__ a) {
    int m = 0;
    int stride = gridDim.x * blockDim.x;
    for (int i = blockIdx.x * blockDim.x + threadIdx.x; i < N_NODES; i += stride)
        m = max(m, a[i]);
    #pragma unroll
    for (int s = 16; s > 0; s >>= 1)
        m = max(m, __shfl_xor_sync(0xffffffffu, m, s));
    if ((threadIdx.x & 31) == 0) atomicMax(&g_isy, m);
}

__global__ void canon_kernel(const int* __restrict__ a, const int* __restrict__ b) {
    bool a_is_y = (g_isy > 1);
    const int* yp = a_is_y ? a : b;
    const int* tp = a_is_y ? b : a;
    int stride = gridDim.x * blockDim.x;
    for (int i = blockIdx.x * blockDim.x + threadIdx.x; i < N_NODES; i += stride) {
        g_y[i] = yp[i];
        g_tm[i] = tp[i];
    }
}

__global__ void count_kernel(const int* __restrict__ row) {
    int stride = gridDim.x * blockDim.x;
    for (int e = blockIdx.x * blockDim.x + threadIdx.x; e < N_EDGES; e += stride)
        atomicAdd(&g_ecnt[row[e]], 1);
    for (int i = blockIdx.x * blockDim.x + threadIdx.x; i < N_NODES; i += stride)
        if (g_tm[i]) atomicAdd(&g_classcnt[g_y[i]], 1);
}

__global__ void scan1_kernel() {
    __shared__ int s[SCAN_BLK];
    int gid = blockIdx.x * SCAN_BLK + threadIdx.x;
    int val = (gid < N_NODES) ? g_ecnt[gid] : 0;
    s[threadIdx.x] = val;
    __syncthreads();
    for (int d = 1; d < SCAN_BLK; d <<= 1) {
        int t = (threadIdx.x >= (unsigned)d) ? s[threadIdx.x - d] : 0;
        __syncthreads();
        s[threadIdx.x] += t;
        __syncthreads();
    }
    if (gid < N_NODES) g_off[gid] = s[threadIdx.x] - val;  // exclusive
    if (threadIdx.x == SCAN_BLK - 1) g_blocksums[blockIdx.x] = s[SCAN_BLK - 1];
}

// block-level scan of 98 block sums — single block, shared-memory scan
__global__ void scan2_kernel() {
    __shared__ int s[128];
    int v = (threadIdx.x < N_SCAN_BLOCKS) ? g_blocksums[threadIdx.x] : 0;
    s[threadIdx.x] = v;
    __syncthreads();
    for (int d = 1; d < 128; d <<= 1) {
        int t = (threadIdx.x >= (unsigned)d) ? s[threadIdx.x - d] : 0;
        __syncthreads();
        s[threadIdx.x] += t;
        __syncthreads();
    }
    if (threadIdx.x < N_SCAN_BLOCKS)
        g_blocksums[threadIdx.x] = s[threadIdx.x] - v;   // exclusive
}

__global__ void scan3_kernel() {
    int stride = gridDim.x * blockDim.x;
    for (int i = blockIdx.x * blockDim.x + threadIdx.x; i < N_NODES; i += stride) {
        g_off[i] += g_blocksums[i >> 10];
        g_deginv[i] = 1.0f / (float)(g_ecnt[i] + 1);   // +1 self loop
    }
}

__global__ void scatter_kernel(const int* __restrict__ row,
                               const int* __restrict__ col) {
    int stride = gridDim.x * blockDim.x;
    for (int e = blockIdx.x * blockDim.x + threadIdx.x; e < N_EDGES; e += stride) {
        int r = row[e];
        int pos = g_off[r] + atomicAdd(&g_cursor[r], 1);
        g_colidx[pos] = col[e];
    }
}

__global__ void colsum_kernel(const float* __restrict__ x) {
    __shared__ float s[D];
    if (threadIdx.x < D) s[threadIdx.x] = 0.0f;
    __syncthreads();
    float acc = 0.0f;
    int stride = gridDim.x * blockDim.x;  // multiple of 64 -> fixed column per thread
    for (int idx = blockIdx.x * blockDim.x + threadIdx.x; idx < N_NODES * D; idx += stride)
        acc += x[idx];
    atomicAdd(&s[threadIdx.x & (D - 1)], acc);
    __syncthreads();
    if (threadIdx.x < D) atomicAdd(&g_colsum[threadIdx.x], s[threadIdx.x]);
}

// center features; seed v0; bootstrap cs[0] = Y^T xc; compute lblscale
__global__ void init_kernel(const float* __restrict__ x) {
    int stride = gridDim.x * blockDim.x;
    const float invn = 1.0f / (float)N_NODES;
    for (int idx = blockIdx.x * blockDim.x + threadIdx.x; idx < N_NODES * D; idx += stride) {
        int i = idx >> 6;
        int d = idx & (D - 1);
        float v = x[idx] - g_colsum[d] * invn;
        g_xc[idx] = v;
        g_v0[idx] = v;
        if (g_tm[i]) atomicAdd(&g_cs3[0][g_y[i] * D + d], v);
    }
    for (int i = blockIdx.x * blockDim.x + threadIdx.x; i < N_NODES; i += stride)
        g_lblscale[i] = g_tm[i] ? 1.0f / ((float)g_classcnt[g_y[i]] + 1e-8f) : 0.0f;
}

// ---------- fused power iteration ----------
// Warp per node. Reads cs3[it%3], writes v_{t+1}, accumulates cs3[(it+1)%3]
// from its output (class sums for the NEXT iteration), block 0 zeroes
// cs3[(it+2)%3] for the iteration after that.
__global__ __launch_bounds__(256) void power_iter_kernel(int it) {
    const int pin = it % 3;
    const int pacc = (it + 1) % 3;
    const int pzero = (it + 2) % 3;
    const float* __restrict__ vin = (it & 1) ? g_v1 : g_v0;
    float* __restrict__ vout = (it & 1) ? g_v0 : g_v1;

    if (blockIdx.x == 0) {
        for (int i = threadIdx.x; i < C_CLS * D; i += blockDim.x)
            g_cs3[pzero][i] = 0.0f;
    }

    int warp = (blockIdx.x * blockDim.x + threadIdx.x) >> 5;
    int lane = threadIdx.x & 31;
    if (warp >= N_NODES) return;
    const int i = warp;
    const float2* __restrict__ v2 = (const float2*)vin;

    float2 acc = v2[i * 32 + lane];  // self-loop contribution
    int off = g_off[i];
    int cnt = g_ecnt[i];

    // chunked gather, 16 edges per chunk, all loads issued before accumulation
    for (int base = 0; base < cnt; base += 16) {
        int rem = cnt - base;                       // > 0
        int idx = 0;                                // safe padding index (row 0)
        if (lane < 16 && lane < rem) idx = g_colidx[off + base + lane];
        float2 t[16];
        #pragma unroll
        for (int k = 0; k < 16; k++) {
            int j = __shfl_sync(0xffffffffu, idx, k);
            t[k] = v2[j * 32 + lane];
        }
        #pragma unroll
        for (int k = 0; k < 16; k++) {
            if (k < rem) { acc.x += t[k].x; acc.y += t[k].y; }
        }
    }

    float dinv = g_deginv[i];
    float ls = g_lblscale[i];
    int yv = 0;
    float2 p2 = make_float2(0.0f, 0.0f);
    if (ls != 0.0f) {
        yv = g_y[i];
        const float2* cs2 = (const float2*)g_cs3[pin];
        p2 = cs2[yv * 32 + lane];
    }
    const float2* xc2 = (const float2*)g_xc;
    float2 xcv = xc2[i * 32 + lane];
    float2 o;
    o.x = 0.45f * dinv * acc.x + 0.05f * ls * p2.x + 0.5f * xcv.x;
    o.y = 0.45f * dinv * acc.y + 0.05f * ls * p2.y + 0.5f * xcv.y;
    ((float2*)vout)[i * 32 + lane] = o;

    // accumulate class sums of the OUTPUT for the next iteration
    if (ls != 0.0f) {
        float* csn = g_cs3[pacc];
        atomicAdd(&csn[yv * D + 2 * lane], o.x);
        atomicAdd(&csn[yv * D + 2 * lane + 1], o.y);
    }
}

// ---------- final GEMM: out = g_v0 @ W + bias ----------
__global__ __launch_bounds__(256) void gemm_kernel(const float* __restrict__ W,
                                                   const float* __restrict__ bias,
                                                   float* __restrict__ out) {
    __shared__ float sW[D * D];
    __shared__ float sB[D];
    for (int i = threadIdx.x; i < D * D; i += blockDim.x) sW[i] = W[i];
    if (threadIdx.x < D) sB[threadIdx.x] = bias[threadIdx.x];
    __syncthreads();
    int warp = (blockIdx.x * blockDim.x + threadIdx.x) >> 5;
    int lane = threadIdx.x & 31;
    if (warp >= N_NODES) return;
    const float2* v2 = (const float2*)g_v0;
    float2 myv = v2[warp * 32 + lane];
    float2 acc = make_float2(sB[2 * lane], sB[2 * lane + 1]);
    #pragma unroll
    for (int k = 0; k < 32; k++) {
        float a = __shfl_sync(0xffffffffu, myv.x, k);  // v[i][2k]
        float b = __shfl_sync(0xffffffffu, myv.y, k);  // v[i][2k+1]
        acc.x += a * sW[(2 * k) * D + 2 * lane]     + b * sW[(2 * k + 1) * D + 2 * lane];
        acc.y += a * sW[(2 * k) * D + 2 * lane + 1] + b * sW[(2 * k + 1) * D + 2 * lane + 1];
    }
    ((float2*)out)[warp * 32 + lane] = acc;
}

// ---------- launch ----------
extern "C" void kernel_launch(void* const* d_in, const int* in_sizes, int n_in,
                              void* d_out, int out_size) {
    // Resolve inputs by unique element counts; the two 100k int arrays (y,
    // train_mask) are disambiguated on-device.
    const float* x = nullptr;
    const float* W = nullptr;
    const float* bias = nullptr;
    const int* ei = nullptr;
    const int* nb[2] = {nullptr, nullptr};
    int nbi = 0;
    for (int i = 0; i < n_in; i++) {
        switch (in_sizes[i]) {
            case N_NODES * D:   x = (const float*)d_in[i]; break;
            case D * D:         W = (const float*)d_in[i]; break;
            case D:             bias = (const float*)d_in[i]; break;
            case 2 * N_EDGES:   ei = (const int*)d_in[i]; break;
            case N_NODES:       if (nbi < 2) nb[nbi++] = (const int*)d_in[i]; break;
            default: break;
        }
    }
    float* out = (float*)d_out;
    const int* row = ei;            // edge_index[0]
    const int* col = ei + N_EDGES;  // edge_index[1]

    // ---- one-time setup ----
    zero_setup_kernel<<<256, 256>>>();
    disamb_kernel<<<128, 256>>>(nb[0]);
    canon_kernel<<<256, 256>>>(nb[0], nb[1]);
    count_kernel<<<512, 256>>>(row);
    scan1_kernel<<<N_SCAN_BLOCKS, SCAN_BLK>>>();
    scan2_kernel<<<1, 128>>>();
    scan3_kernel<<<256, 256>>>();
    scatter_kernel<<<512, 256>>>(row, col);
    colsum_kernel<<<256, 256>>>(x);
    init_kernel<<<512, 256>>>(x);

    // ---- 50 fused power iterations (1 launch each) ----
    const int bblocks = (N_NODES * 32 + 255) / 256;  // warp per node
    for (int it = 0; it < N_POW; it++)
        power_iter_kernel<<<bblocks, 256>>>(it);

    // 50 iterations (even) => result is in g_v0
    gemm_kernel<<<bblocks, 256>>>(W, bias, out);
}